// round 1
// baseline (speedup 1.0000x reference)
#include <cuda_runtime.h>

#define N_NODES 50000
#define N_EDGES 800000
#define C 128
#define KCHEB 6
#define NB_SCAN ((N_NODES + 1023) / 1024)

// ---------------- scratch (device globals: no allocation allowed) ----------------
__device__ float    g_deg[N_NODES];
__device__ int      g_cnt[N_NODES];
__device__ int      g_rowptr[N_NODES + 1];
__device__ int      g_next[N_NODES];
__device__ int      g_part[64];
__device__ int      g_csr_recv[N_EDGES];
__device__ float    g_csr_w[N_EDGES];
__device__ float    g_bufA[(size_t)N_NODES * C];
__device__ float    g_bufB[(size_t)N_NODES * C];
__device__ unsigned g_maxkey;
__device__ float    g_scale2[2];   // {scale, 2*scale}
__device__ float    g_bsum[C];     // sum_k b_dense[k] + bias

// monotone float <-> uint key (total order under unsigned compare)
__device__ __forceinline__ unsigned fkey(float f) {
    unsigned u = __float_as_uint(f);
    return (u & 0x80000000u) ? ~u : (u | 0x80000000u);
}
__device__ __forceinline__ float funkey(unsigned k) {
    return (k & 0x80000000u) ? __uint_as_float(k & 0x7fffffffu)
                             : __uint_as_float(~k);
}

// full-block max-reduce of a key, then one atomicMax per block
__device__ __forceinline__ void blockMaxKey(unsigned k) {
    int lane = threadIdx.x & 31, wid = threadIdx.x >> 5;
    #pragma unroll
    for (int o = 16; o > 0; o >>= 1) {
        unsigned other = __shfl_down_sync(0xffffffffu, k, o);
        k = k > other ? k : other;
    }
    __shared__ unsigned sm[32];
    if (lane == 0) sm[wid] = k;
    __syncthreads();
    if (wid == 0) {
        int nw = (blockDim.x + 31) >> 5;
        k = (lane < nw) ? sm[lane] : 0u;
        #pragma unroll
        for (int o = 16; o > 0; o >>= 1) {
            unsigned other = __shfl_down_sync(0xffffffffu, k, o);
            k = k > other ? k : other;
        }
        if (lane == 0) atomicMax(&g_maxkey, k);
    }
}

// ---------------- setup kernels ----------------
__global__ void k_init(const float* __restrict__ bd, const float* __restrict__ bias) {
    int i = blockIdx.x * blockDim.x + threadIdx.x;
    if (i < N_NODES) { g_deg[i] = 0.f; g_cnt[i] = 0; }
    if (i < C) {
        float s = bias[i];
        #pragma unroll
        for (int k = 0; k < KCHEB; k++) s += bd[k * C + i];
        g_bsum[i] = s;
    }
    if (i == 0) g_maxkey = 0u;
}

__global__ void k_edge_stats(const float* __restrict__ edges, const int* __restrict__ senders) {
    int e = blockIdx.x * blockDim.x + threadIdx.x;
    unsigned key = 0u;
    if (e < N_EDGES) {
        float w = edges[e];
        int s = senders[e];
        atomicAdd(&g_deg[s], w);
        atomicAdd(&g_cnt[s], 1);
        key = fkey(-w);
    }
    blockMaxKey(key);
}

__global__ void k_deg_max() {
    int i = blockIdx.x * blockDim.x + threadIdx.x;
    unsigned key = (i < N_NODES) ? fkey(g_deg[i]) : 0u;
    blockMaxKey(key);
}

__global__ void k_finalize() {
    float m = funkey(g_maxkey);          // lambda_max = 2*m, scale = 2/lambda_max = 1/m
    g_scale2[0] = 1.0f / m;
    g_scale2[1] = 2.0f / m;
}

// block-local exclusive scan (1024 threads) + per-block totals
__global__ void k_scan1() {
    int t = threadIdx.x;
    int i = blockIdx.x * 1024 + t;
    int v = (i < N_NODES) ? g_cnt[i] : 0;
    int lane = t & 31, wid = t >> 5;
    int incl = v;
    #pragma unroll
    for (int o = 1; o < 32; o <<= 1) {
        int n = __shfl_up_sync(0xffffffffu, incl, o);
        if (lane >= o) incl += n;
    }
    __shared__ int ws[32];
    if (lane == 31) ws[wid] = incl;
    __syncthreads();
    if (wid == 0) {
        int x = ws[lane];
        int ix = x;
        #pragma unroll
        for (int o = 1; o < 32; o <<= 1) {
            int n = __shfl_up_sync(0xffffffffu, ix, o);
            if (lane >= o) ix += n;
        }
        ws[lane] = ix - x;  // exclusive warp offsets
    }
    __syncthreads();
    int excl = incl - v + ws[wid];
    if (i < N_NODES) g_rowptr[i] = excl;
    if (t == 1023) g_part[blockIdx.x] = excl + v;
}

__global__ void k_scan2() {
    if (threadIdx.x == 0) {
        int c = 0;
        for (int b = 0; b < NB_SCAN; b++) { int v = g_part[b]; g_part[b] = c; c += v; }
        g_rowptr[N_NODES] = c;
    }
}

__global__ void k_scan3() {
    int i = blockIdx.x * blockDim.x + threadIdx.x;
    if (i < N_NODES) {
        int rp = g_rowptr[i] + g_part[i >> 10];
        g_rowptr[i] = rp;
        g_next[i] = rp;
    }
}

__global__ void k_fill(const int* __restrict__ senders, const int* __restrict__ receivers,
                       const float* __restrict__ edges) {
    int e = blockIdx.x * blockDim.x + threadIdx.x;
    if (e < N_EDGES) {
        int s = senders[e];
        int p = atomicAdd(&g_next[s], 1);
        g_csr_recv[p] = receivers[e];
        g_csr_w[p] = edges[e];
    }
}

// ---------------- fused Laplacian matvec + Chebyshev combine ----------------
// out = scale2[mode] * (deg*x - sum_e w_e * x[recv_e]) - (mode ? prev : 0)
__device__ __forceinline__ const float* sel_in(const float* nodes, int s) {
    return s == 0 ? nodes : (s == 1 ? (const float*)g_bufA : (const float*)g_bufB);
}

__global__ __launch_bounds__(256) void k_spmv(const float* __restrict__ nodes,
                                              int in_sel, int prev_sel, int out_sel, int mode) {
    const float* x = sel_in(nodes, in_sel);
    const float* prev = sel_in(nodes, prev_sel);
    float* o = out_sel == 1 ? g_bufA : g_bufB;

    int warp = (blockIdx.x * blockDim.x + threadIdx.x) >> 5;
    int lane = threadIdx.x & 31;
    if (warp >= N_NODES) return;

    int beg = g_rowptr[warp], end = g_rowptr[warp + 1];
    int c4 = lane * 4;
    float4 acc = make_float4(0.f, 0.f, 0.f, 0.f);

    int e = beg;
    for (; e + 2 <= end; e += 2) {
        int r0 = g_csr_recv[e], r1 = g_csr_recv[e + 1];
        float w0 = g_csr_w[e], w1 = g_csr_w[e + 1];
        float4 a = *(const float4*)(x + (size_t)r0 * C + c4);
        float4 b = *(const float4*)(x + (size_t)r1 * C + c4);
        acc.x += w0 * a.x + w1 * b.x;
        acc.y += w0 * a.y + w1 * b.y;
        acc.z += w0 * a.z + w1 * b.z;
        acc.w += w0 * a.w + w1 * b.w;
    }
    if (e < end) {
        int r0 = g_csr_recv[e];
        float w0 = g_csr_w[e];
        float4 a = *(const float4*)(x + (size_t)r0 * C + c4);
        acc.x += w0 * a.x; acc.y += w0 * a.y; acc.z += w0 * a.z; acc.w += w0 * a.w;
    }

    float s = g_scale2[mode];
    float d = g_deg[warp];
    float4 xv = *(const float4*)(x + (size_t)warp * C + c4);
    float4 r;
    r.x = s * (d * xv.x - acc.x);
    r.y = s * (d * xv.y - acc.y);
    r.z = s * (d * xv.z - acc.z);
    r.w = s * (d * xv.w - acc.w);
    if (mode) {
        float4 p = *(const float4*)(prev + (size_t)warp * C + c4);
        r.x -= p.x; r.y -= p.y; r.z -= p.z; r.w -= p.w;
    }
    *(float4*)(o + (size_t)warp * C + c4) = r;
}

// ---------------- GEMM: out (+)= X @ W  (50000x128 @ 128x128) ----------------
__global__ __launch_bounds__(256, 2) void k_gemm(const float* __restrict__ nodes, int in_sel,
                                                 const float* __restrict__ Wp,
                                                 float* __restrict__ out, int first) {
    const float* X = sel_in(nodes, in_sel);
    __shared__ float Ws[16 * 128];
    __shared__ float Xs[16 * 132];  // padded stride

    int tid = threadIdx.x;
    int tx = tid & 15, ty = tid >> 4;
    int row0 = blockIdx.x * 128;

    float acc[8][8];
    #pragma unroll
    for (int i = 0; i < 8; i++)
        #pragma unroll
        for (int j = 0; j < 8; j++) acc[i][j] = 0.f;

    for (int k0 = 0; k0 < 128; k0 += 16) {
        // load W chunk (16x128), coalesced
        #pragma unroll
        for (int t2 = tid; t2 < 512; t2 += 256) {
            int kk = t2 >> 5, q = t2 & 31;
            *(float4*)&Ws[kk * 128 + q * 4] = *(const float4*)&Wp[(k0 + kk) * 128 + q * 4];
        }
        // load X chunk transposed: Xs[k][r]
        #pragma unroll
        for (int t2 = tid; t2 < 512; t2 += 256) {
            int r = t2 >> 2, q = t2 & 3;
            int row = row0 + r;
            float4 v = make_float4(0.f, 0.f, 0.f, 0.f);
            if (row < N_NODES) v = *(const float4*)&X[(size_t)row * C + k0 + q * 4];
            Xs[(q * 4 + 0) * 132 + r] = v.x;
            Xs[(q * 4 + 1) * 132 + r] = v.y;
            Xs[(q * 4 + 2) * 132 + r] = v.z;
            Xs[(q * 4 + 3) * 132 + r] = v.w;
        }
        __syncthreads();
        #pragma unroll
        for (int kk = 0; kk < 16; kk++) {
            float xf[8], wf[8];
            *(float4*)&xf[0] = *(float4*)&Xs[kk * 132 + ty * 8];
            *(float4*)&xf[4] = *(float4*)&Xs[kk * 132 + ty * 8 + 4];
            *(float4*)&wf[0] = *(float4*)&Ws[kk * 128 + tx * 8];
            *(float4*)&wf[4] = *(float4*)&Ws[kk * 128 + tx * 8 + 4];
            #pragma unroll
            for (int i = 0; i < 8; i++)
                #pragma unroll
                for (int j = 0; j < 8; j++) acc[i][j] += xf[i] * wf[j];
        }
        __syncthreads();
    }

    #pragma unroll
    for (int i = 0; i < 8; i++) {
        int row = row0 + ty * 8 + i;
        if (row >= N_NODES) break;
        float* op = out + (size_t)row * C + tx * 8;
        #pragma unroll
        for (int j = 0; j < 8; j += 4) {
            float4 o4;
            if (first) {
                o4.x = acc[i][j + 0] + g_bsum[tx * 8 + j + 0];
                o4.y = acc[i][j + 1] + g_bsum[tx * 8 + j + 1];
                o4.z = acc[i][j + 2] + g_bsum[tx * 8 + j + 2];
                o4.w = acc[i][j + 3] + g_bsum[tx * 8 + j + 3];
            } else {
                float4 cur = *(float4*)&op[j];
                o4.x = cur.x + acc[i][j + 0];
                o4.y = cur.y + acc[i][j + 1];
                o4.z = cur.z + acc[i][j + 2];
                o4.w = cur.w + acc[i][j + 3];
            }
            *(float4*)&op[j] = o4;
        }
    }
}

// ---------------- launch ----------------
extern "C" void kernel_launch(void* const* d_in, const int* in_sizes, int n_in,
                              void* d_out, int out_size) {
    const float* nodes     = (const float*)d_in[0];
    const float* edges     = (const float*)d_in[1];
    const int*   senders   = (const int*)d_in[2];
    const int*   receivers = (const int*)d_in[3];
    const float* W         = (const float*)d_in[4];
    const float* b_dense   = (const float*)d_in[5];
    const float* bias      = (const float*)d_in[6];
    float* out = (float*)d_out;

    const int NBLK_N = (N_NODES + 255) / 256;   // 196
    const int NBLK_E = (N_EDGES + 255) / 256;   // 3125
    const int NBLK_G = (N_NODES + 127) / 128;   // 391
    const int NBLK_S = (N_NODES * 32 + 255) / 256;  // 6250

    k_init<<<NBLK_N, 256>>>(b_dense, bias);
    k_edge_stats<<<NBLK_E, 256>>>(edges, senders);
    k_deg_max<<<NBLK_N, 256>>>();
    k_finalize<<<1, 1>>>();
    k_scan1<<<NB_SCAN, 1024>>>();
    k_scan2<<<1, 32>>>();
    k_scan3<<<NBLK_N, 256>>>();
    k_fill<<<NBLK_E, 256>>>(senders, receivers, edges);

    // k = 0: out = nodes @ W0 + (sum_k b_dense[k] + bias)
    k_gemm<<<NBLK_G, 256>>>(nodes, 0, W + 0 * C * C, out, 1);
    // Tx1 = scale * L * nodes  -> bufB
    k_spmv<<<NBLK_S, 256>>>(nodes, 0, 0, 2, 0);
    k_gemm<<<NBLK_G, 256>>>(nodes, 2, W + 1 * C * C, out, 0);
    // Tx2 = 2 scale L Tx1 - Tx0 -> bufA
    k_spmv<<<NBLK_S, 256>>>(nodes, 2, 0, 1, 1);
    k_gemm<<<NBLK_G, 256>>>(nodes, 1, W + 2 * C * C, out, 0);
    // Tx3 -> bufB (in-place over Tx1; gathers read bufA)
    k_spmv<<<NBLK_S, 256>>>(nodes, 1, 2, 2, 1);
    k_gemm<<<NBLK_G, 256>>>(nodes, 2, W + 3 * C * C, out, 0);
    // Tx4 -> bufA
    k_spmv<<<NBLK_S, 256>>>(nodes, 2, 1, 1, 1);
    k_gemm<<<NBLK_G, 256>>>(nodes, 1, W + 4 * C * C, out, 0);
    // Tx5 -> bufB
    k_spmv<<<NBLK_S, 256>>>(nodes, 1, 2, 2, 1);
    k_gemm<<<NBLK_G, 256>>>(nodes, 2, W + 5 * C * C, out, 0);
}

// round 3
// speedup vs baseline: 1.7095x; 1.7095x over previous
#include <cuda_runtime.h>
#include <cstdint>

#define N_NODES 50000
#define N_EDGES 800000
#define C 128
#define KCHEB 6
#define NB_SCAN ((N_NODES + 1023) / 1024)
#define NTILES ((N_NODES + 127) / 128)

// ---------------- scratch (device globals: no allocation allowed) ----------------
__device__ float    g_deg[N_NODES];
__device__ int      g_cnt[N_NODES];
__device__ int      g_rowptr[N_NODES + 1];
__device__ int      g_next[N_NODES];
__device__ int      g_part[64];
__device__ int      g_csr_recv[N_EDGES];
__device__ float    g_csr_w[N_EDGES];
__device__ float    g_T[5][N_NODES * C];       // Tx1..Tx5
__device__ float    g_WT[KCHEB * C * C];       // WT[k][n][cin] = W[k][cin][n]
__device__ unsigned g_maxkey;
__device__ float    g_scale2[2];               // {scale, 2*scale}
__device__ float    g_bsum[C];                 // sum_k b_dense[k] + bias

// ---------------- helpers ----------------
__device__ __forceinline__ unsigned fkey(float f) {
    unsigned u = __float_as_uint(f);
    return (u & 0x80000000u) ? ~u : (u | 0x80000000u);
}
__device__ __forceinline__ float funkey(unsigned k) {
    return (k & 0x80000000u) ? __uint_as_float(k & 0x7fffffffu) : __uint_as_float(~k);
}

__device__ __forceinline__ void blockMaxKey(unsigned k) {
    int lane = threadIdx.x & 31, wid = threadIdx.x >> 5;
    #pragma unroll
    for (int o = 16; o > 0; o >>= 1) {
        unsigned x = __shfl_down_sync(0xffffffffu, k, o);
        k = k > x ? k : x;
    }
    __shared__ unsigned sm[32];
    if (lane == 0) sm[wid] = k;
    __syncthreads();
    if (wid == 0) {
        int nw = (blockDim.x + 31) >> 5;
        k = (lane < nw) ? sm[lane] : 0u;
        #pragma unroll
        for (int o = 16; o > 0; o >>= 1) {
            unsigned x = __shfl_down_sync(0xffffffffu, k, o);
            k = k > x ? k : x;
        }
        if (lane == 0) atomicMax(&g_maxkey, k);
    }
}

__device__ __forceinline__ uint32_t f2tf(float f) {
    uint32_t r;
    asm("cvt.rna.tf32.f32 %0, %1;" : "=r"(r) : "f"(f));
    return r;
}

__device__ __forceinline__ void mma_tf32(float* c, uint32_t a0, uint32_t a1,
                                         uint32_t a2, uint32_t a3,
                                         uint32_t b0, uint32_t b1) {
    asm volatile(
        "mma.sync.aligned.m16n8k8.row.col.f32.tf32.tf32.f32 "
        "{%0,%1,%2,%3}, {%4,%5,%6,%7}, {%8,%9}, {%0,%1,%2,%3};"
        : "+f"(c[0]), "+f"(c[1]), "+f"(c[2]), "+f"(c[3])
        : "r"(a0), "r"(a1), "r"(a2), "r"(a3), "r"(b0), "r"(b1));
}

// ---------------- setup kernels ----------------
__global__ void k_init(const float* __restrict__ bd, const float* __restrict__ bias) {
    int i = blockIdx.x * blockDim.x + threadIdx.x;
    if (i < N_NODES) { g_deg[i] = 0.f; g_cnt[i] = 0; }
    if (i < C) {
        float s = bias[i];
        #pragma unroll
        for (int k = 0; k < KCHEB; k++) s += bd[k * C + i];
        g_bsum[i] = s;
    }
    if (i == 0) g_maxkey = 0u;
}

__global__ void k_edge_stats(const float* __restrict__ edges, const int* __restrict__ senders) {
    int e = blockIdx.x * blockDim.x + threadIdx.x;
    unsigned key = 0u;
    if (e < N_EDGES) {
        float w = edges[e];
        int s = senders[e];
        atomicAdd(&g_deg[s], w);
        atomicAdd(&g_cnt[s], 1);
        key = fkey(-w);
    }
    blockMaxKey(key);
}

__global__ void k_deg_max() {
    int i = blockIdx.x * blockDim.x + threadIdx.x;
    unsigned key = (i < N_NODES) ? fkey(g_deg[i]) : 0u;
    blockMaxKey(key);
}

__global__ void k_finalize() {
    float m = funkey(g_maxkey);
    g_scale2[0] = 1.0f / m;
    g_scale2[1] = 2.0f / m;
}

__global__ void k_scan1() {
    int t = threadIdx.x;
    int i = blockIdx.x * 1024 + t;
    int v = (i < N_NODES) ? g_cnt[i] : 0;
    int lane = t & 31, wid = t >> 5;
    int incl = v;
    #pragma unroll
    for (int o = 1; o < 32; o <<= 1) {
        int n = __shfl_up_sync(0xffffffffu, incl, o);
        if (lane >= o) incl += n;
    }
    __shared__ int ws[32];
    if (lane == 31) ws[wid] = incl;
    __syncthreads();
    if (wid == 0) {
        int x = ws[lane];
        int ix = x;
        #pragma unroll
        for (int o = 1; o < 32; o <<= 1) {
            int n = __shfl_up_sync(0xffffffffu, ix, o);
            if (lane >= o) ix += n;
        }
        ws[lane] = ix - x;
    }
    __syncthreads();
    int excl = incl - v + ws[wid];
    if (i < N_NODES) g_rowptr[i] = excl;
    if (t == 1023) g_part[blockIdx.x] = excl + v;
}

__global__ void k_scan2() {
    if (threadIdx.x == 0) {
        int c = 0;
        for (int b = 0; b < NB_SCAN; b++) { int v = g_part[b]; g_part[b] = c; c += v; }
        g_rowptr[N_NODES] = c;
    }
}

__global__ void k_scan3() {
    int i = blockIdx.x * blockDim.x + threadIdx.x;
    if (i < N_NODES) {
        int rp = g_rowptr[i] + g_part[i >> 10];
        g_rowptr[i] = rp;
        g_next[i] = rp;
    }
}

__global__ void k_fill(const int* __restrict__ senders, const int* __restrict__ receivers,
                       const float* __restrict__ edges) {
    int e = blockIdx.x * blockDim.x + threadIdx.x;
    if (e < N_EDGES) {
        int s = senders[e];
        int p = atomicAdd(&g_next[s], 1);
        g_csr_recv[p] = receivers[e];
        g_csr_w[p] = edges[e];
    }
}

// WT[k][n][cin] = W[k][cin][n]
__global__ void k_transW(const float* __restrict__ W) {
    int idx = blockIdx.x * blockDim.x + threadIdx.x;
    if (idx < KCHEB * C * C) {
        int kc = idx >> 14;
        int rem = idx & 16383;
        int n = rem >> 7, k = rem & 127;
        g_WT[idx] = W[kc * C * C + k * C + n];
    }
}

// ---------------- fused Laplacian matvec + Chebyshev combine ----------------
__device__ __forceinline__ const float* selp(const float* nodes, int s) {
    return s == 0 ? nodes : &g_T[s - 1][0];
}

__global__ __launch_bounds__(256) void k_spmv(const float* __restrict__ nodes,
                                              int in_sel, int prev_sel, int out_sel, int mode) {
    const float* x = selp(nodes, in_sel);
    const float* prev = selp(nodes, prev_sel);
    float* o = &g_T[out_sel - 1][0];

    int warp = (blockIdx.x * blockDim.x + threadIdx.x) >> 5;
    int lane = threadIdx.x & 31;
    if (warp >= N_NODES) return;

    int beg = g_rowptr[warp], end = g_rowptr[warp + 1];
    int c4 = lane * 4;
    float4 acc = make_float4(0.f, 0.f, 0.f, 0.f);

    int e = beg;
    for (; e + 2 <= end; e += 2) {
        int r0 = g_csr_recv[e], r1 = g_csr_recv[e + 1];
        float w0 = g_csr_w[e], w1 = g_csr_w[e + 1];
        float4 a = *(const float4*)(x + (size_t)r0 * C + c4);
        float4 b = *(const float4*)(x + (size_t)r1 * C + c4);
        acc.x += w0 * a.x + w1 * b.x;
        acc.y += w0 * a.y + w1 * b.y;
        acc.z += w0 * a.z + w1 * b.z;
        acc.w += w0 * a.w + w1 * b.w;
    }
    if (e < end) {
        int r0 = g_csr_recv[e];
        float w0 = g_csr_w[e];
        float4 a = *(const float4*)(x + (size_t)r0 * C + c4);
        acc.x += w0 * a.x; acc.y += w0 * a.y; acc.z += w0 * a.z; acc.w += w0 * a.w;
    }

    float s = g_scale2[mode];
    float d = g_deg[warp];
    float4 xv = *(const float4*)(x + (size_t)warp * C + c4);
    float4 r;
    r.x = s * (d * xv.x - acc.x);
    r.y = s * (d * xv.y - acc.y);
    r.z = s * (d * xv.z - acc.z);
    r.w = s * (d * xv.w - acc.w);
    if (mode) {
        float4 p = *(const float4*)(prev + (size_t)warp * C + c4);
        r.x -= p.x; r.y -= p.y; r.z -= p.z; r.w -= p.w;
    }
    *(float4*)(o + (size_t)warp * C + c4) = r;
}

// ---------------- fused tf32 mma.sync GEMM: out = sum_k Tx_k @ W_k + bsum -------
// CTA: 128 rows x 128 cols output, 512 threads (16 warps, warp tile 32x32).
// Xs[row][k] stride 132, Ws[n][k] stride 132 (tf32 bits), conflict-free frag loads.
#define XS_STRIDE 132
#define SMEM_GEMM_BYTES (2 * 128 * XS_STRIDE * 4)

__global__ __launch_bounds__(512) void k_mma_gemm(const float* __restrict__ nodes,
                                                  float* __restrict__ out) {
    extern __shared__ uint32_t smu[];
    uint32_t* Xs = smu;                    // [128][132]
    uint32_t* Ws = smu + 128 * XS_STRIDE;  // [128][132]

    int tid = threadIdx.x;
    int wid = tid >> 5, lane = tid & 31;
    int g = lane >> 2, t = lane & 3;       // groupID, threadID_in_group
    int wm = wid & 3, wn = wid >> 2;       // warp tile: rows wm*32, cols wn*32
    int row0 = blockIdx.x * 128;

    float acc[2][4][4];
    #pragma unroll
    for (int mt = 0; mt < 2; mt++)
        #pragma unroll
        for (int nt = 0; nt < 4; nt++)
            #pragma unroll
            for (int j = 0; j < 4; j++) acc[mt][nt][j] = 0.f;

    for (int kc = 0; kc < KCHEB; kc++) {
        const float* Xp = (kc == 0) ? nodes : &g_T[kc - 1][0];
        const float* Wp = g_WT + kc * (C * C);

        // stage X tile (rows row0..row0+127) and W tile, converted to tf32
        #pragma unroll
        for (int i = 0; i < 8; i++) {
            int idx = tid + i * 512;
            int r = idx >> 5;
            int k = (idx & 31) * 4;
            int row = row0 + r;
            float4 xv = make_float4(0.f, 0.f, 0.f, 0.f);
            if (row < N_NODES) xv = *(const float4*)(Xp + (size_t)row * C + k);
            uint4 xt = make_uint4(f2tf(xv.x), f2tf(xv.y), f2tf(xv.z), f2tf(xv.w));
            *(uint4*)(Xs + r * XS_STRIDE + k) = xt;

            float4 wv = *(const float4*)(Wp + r * C + k);
            uint4 wt = make_uint4(f2tf(wv.x), f2tf(wv.y), f2tf(wv.z), f2tf(wv.w));
            *(uint4*)(Ws + r * XS_STRIDE + k) = wt;
        }
        __syncthreads();

        #pragma unroll
        for (int ks = 0; ks < 16; ks++) {
            int kb = ks * 8;
            uint32_t a[2][4];
            #pragma unroll
            for (int mt = 0; mt < 2; mt++) {
                int r = wm * 32 + mt * 16 + g;
                const uint32_t* xr = Xs + r * XS_STRIDE + kb;
                a[mt][0] = xr[t];
                a[mt][1] = xr[8 * XS_STRIDE + t];
                a[mt][2] = xr[t + 4];
                a[mt][3] = xr[8 * XS_STRIDE + t + 4];
            }
            #pragma unroll
            for (int nt = 0; nt < 4; nt++) {
                int n = wn * 32 + nt * 8 + g;
                const uint32_t* wr = Ws + n * XS_STRIDE + kb;
                uint32_t b0 = wr[t];
                uint32_t b1 = wr[t + 4];
                mma_tf32(acc[0][nt], a[0][0], a[0][1], a[0][2], a[0][3], b0, b1);
                mma_tf32(acc[1][nt], a[1][0], a[1][1], a[1][2], a[1][3], b0, b1);
            }
        }
        __syncthreads();
    }

    // epilogue: D(row, col) with bias
    #pragma unroll
    for (int mt = 0; mt < 2; mt++) {
        int row_lo = row0 + wm * 32 + mt * 16 + g;
        int row_hi = row_lo + 8;
        #pragma unroll
        for (int nt = 0; nt < 4; nt++) {
            int col = wn * 32 + nt * 8 + 2 * t;
            float b0 = g_bsum[col], b1 = g_bsum[col + 1];
            if (row_lo < N_NODES) {
                float2 v = make_float2(acc[mt][nt][0] + b0, acc[mt][nt][1] + b1);
                *(float2*)(out + (size_t)row_lo * C + col) = v;
            }
            if (row_hi < N_NODES) {
                float2 v = make_float2(acc[mt][nt][2] + b0, acc[mt][nt][3] + b1);
                *(float2*)(out + (size_t)row_hi * C + col) = v;
            }
        }
    }
}

// ---------------- launch ----------------
extern "C" void kernel_launch(void* const* d_in, const int* in_sizes, int n_in,
                              void* d_out, int out_size) {
    const float* nodes     = (const float*)d_in[0];
    const float* edges     = (const float*)d_in[1];
    const int*   senders   = (const int*)d_in[2];
    const int*   receivers = (const int*)d_in[3];
    const float* W         = (const float*)d_in[4];
    const float* b_dense   = (const float*)d_in[5];
    const float* bias      = (const float*)d_in[6];
    float* out = (float*)d_out;

    const int NBLK_N = (N_NODES + 255) / 256;
    const int NBLK_E = (N_EDGES + 255) / 256;
    const int NBLK_S = (N_NODES * 32 + 255) / 256;

    cudaFuncSetAttribute(k_mma_gemm, cudaFuncAttributeMaxDynamicSharedMemorySize,
                         SMEM_GEMM_BYTES);

    k_init<<<NBLK_N, 256>>>(b_dense, bias);
    k_edge_stats<<<NBLK_E, 256>>>(edges, senders);
    k_deg_max<<<NBLK_N, 256>>>();
    k_finalize<<<1, 1>>>();
    k_scan1<<<NB_SCAN, 1024>>>();
    k_scan2<<<1, 32>>>();
    k_scan3<<<NBLK_N, 256>>>();
    k_fill<<<NBLK_E, 256>>>(senders, receivers, edges);
    k_transW<<<(KCHEB * C * C + 255) / 256, 256>>>(W);

    // Chebyshev recurrence: T1..T5 into g_T[0..4]
    k_spmv<<<NBLK_S, 256>>>(nodes, 0, 0, 1, 0);
    k_spmv<<<NBLK_S, 256>>>(nodes, 1, 0, 2, 1);
    k_spmv<<<NBLK_S, 256>>>(nodes, 2, 1, 3, 1);
    k_spmv<<<NBLK_S, 256>>>(nodes, 3, 2, 4, 1);
    k_spmv<<<NBLK_S, 256>>>(nodes, 4, 3, 5, 1);

    // out = sum_k Tx_k @ W_k + (sum_k b_dense[k] + bias)
    k_mma_gemm<<<NTILES, 512, SMEM_GEMM_BYTES>>>(nodes, out);
}

// round 4
// speedup vs baseline: 2.3735x; 1.3885x over previous
#include <cuda_runtime.h>
#include <cuda_fp16.h>
#include <cstdint>

#define N_NODES 50000
#define N_EDGES 800000
#define C 128
#define KCHEB 6
#define NB_SCAN ((N_NODES + 1023) / 1024)
#define NTILES ((N_NODES + 127) / 128)

// ---------------- scratch (device globals: no allocation allowed) ----------------
__device__ float    g_deg[N_NODES];
__device__ int      g_cnt[N_NODES];
__device__ int      g_rowptr[N_NODES + 1];
__device__ int      g_next[N_NODES];
__device__ int      g_part[NB_SCAN];
__device__ int      g_csr_recv[N_EDGES];
__device__ float    g_csr_w[N_EDGES];
__device__ __half   g_T16[KCHEB][N_NODES * C];   // T0..T5 in fp16
__device__ __half   g_WT16[KCHEB * C * C];       // WT16[k][n][cin] = W[k][cin][n]
__device__ unsigned g_maxkey;
__device__ float    g_bsum[C];                   // sum_k b_dense[k] + bias

// ---------------- helpers ----------------
__device__ __forceinline__ unsigned fkey(float f) {
    unsigned u = __float_as_uint(f);
    return (u & 0x80000000u) ? ~u : (u | 0x80000000u);
}
__device__ __forceinline__ float funkey(unsigned k) {
    return (k & 0x80000000u) ? __uint_as_float(k & 0x7fffffffu) : __uint_as_float(~k);
}

__device__ __forceinline__ void blockMaxKey(unsigned k) {
    int lane = threadIdx.x & 31, wid = threadIdx.x >> 5;
    #pragma unroll
    for (int o = 16; o > 0; o >>= 1) {
        unsigned x = __shfl_down_sync(0xffffffffu, k, o);
        k = k > x ? k : x;
    }
    __shared__ unsigned sm[32];
    if (lane == 0) sm[wid] = k;
    __syncthreads();
    if (wid == 0) {
        int nw = (blockDim.x + 31) >> 5;
        k = (lane < nw) ? sm[lane] : 0u;
        #pragma unroll
        for (int o = 16; o > 0; o >>= 1) {
            unsigned x = __shfl_down_sync(0xffffffffu, k, o);
            k = k > x ? k : x;
        }
        if (lane == 0) atomicMax(&g_maxkey, k);
    }
}

__device__ __forceinline__ void mma_f16(float* c, uint32_t a0, uint32_t a1,
                                        uint32_t a2, uint32_t a3,
                                        uint32_t b0, uint32_t b1) {
    asm volatile(
        "mma.sync.aligned.m16n8k16.row.col.f32.f16.f16.f32 "
        "{%0,%1,%2,%3}, {%4,%5,%6,%7}, {%8,%9}, {%0,%1,%2,%3};"
        : "+f"(c[0]), "+f"(c[1]), "+f"(c[2]), "+f"(c[3])
        : "r"(a0), "r"(a1), "r"(a2), "r"(a3), "r"(b0), "r"(b1));
}

// ---------------- merged setup: zero, bsum, maxkey, W^T fp16, nodes->fp16 --------
__global__ void k_init(const float* __restrict__ nodes, const float* __restrict__ W,
                       const float* __restrict__ bd, const float* __restrict__ bias) {
    unsigned i = blockIdx.x * blockDim.x + threadIdx.x;
    if (i < (unsigned)(N_NODES * C / 2)) {           // nodes -> g_T16[0] (half2 at a time)
        float2 f = *(const float2*)(nodes + (size_t)i * 2);
        *(__half2*)&g_T16[0][(size_t)i * 2] = __floats2half2_rn(f.x, f.y);
    }
    if (i < (unsigned)(KCHEB * C * C)) {             // WT16[k][n][cin] = W[k][cin][n]
        unsigned kc = i >> 14, rem = i & 16383;
        unsigned n = rem >> 7, k = rem & 127;
        g_WT16[i] = __float2half(W[kc * C * C + k * C + n]);
    }
    if (i < N_NODES) { g_deg[i] = 0.f; g_cnt[i] = 0; }
    if (i < C) {
        float s = bias[i];
        #pragma unroll
        for (int k = 0; k < KCHEB; k++) s += bd[k * C + i];
        g_bsum[i] = s;
    }
    if (i == 0) g_maxkey = 0u;
}

__global__ void k_edge_stats(const float* __restrict__ edges, const int* __restrict__ senders) {
    int e = blockIdx.x * blockDim.x + threadIdx.x;
    unsigned key = 0u;
    if (e < N_EDGES) {
        float w = edges[e];
        int s = senders[e];
        atomicAdd(&g_deg[s], w);
        atomicAdd(&g_cnt[s], 1);
        key = fkey(-w);
    }
    blockMaxKey(key);
}

// block scan of counts + per-block totals + deg max (deg final after edge_stats)
__global__ void k_scan1() {
    int t = threadIdx.x;
    int i = blockIdx.x * 1024 + t;
    int v = (i < N_NODES) ? g_cnt[i] : 0;
    unsigned dkey = (i < N_NODES) ? fkey(g_deg[i]) : 0u;
    int lane = t & 31, wid = t >> 5;
    int incl = v;
    #pragma unroll
    for (int o = 1; o < 32; o <<= 1) {
        int n = __shfl_up_sync(0xffffffffu, incl, o);
        if (lane >= o) incl += n;
    }
    __shared__ int ws[32];
    if (lane == 31) ws[wid] = incl;
    __syncthreads();
    if (wid == 0) {
        int x = ws[lane];
        int ix = x;
        #pragma unroll
        for (int o = 1; o < 32; o <<= 1) {
            int n = __shfl_up_sync(0xffffffffu, ix, o);
            if (lane >= o) ix += n;
        }
        ws[lane] = ix - x;
    }
    __syncthreads();
    int excl = incl - v + ws[wid];
    if (i < N_NODES) g_rowptr[i] = excl;
    if (t == 1023) g_part[blockIdx.x] = excl + v;
    __syncthreads();
    blockMaxKey(dkey);
}

// per-block inline prefix of g_part + rowptr finalize
__global__ void k_scan23() {
    __shared__ int pref[NB_SCAN + 1];
    int t = threadIdx.x;
    __shared__ int raw[NB_SCAN];
    if (t < NB_SCAN) raw[t] = g_part[t];
    __syncthreads();
    if (t == 0) {
        int c = 0;
        for (int b = 0; b < NB_SCAN; b++) { pref[b] = c; c += raw[b]; }
        pref[NB_SCAN] = c;
    }
    __syncthreads();
    int i = blockIdx.x * blockDim.x + t;
    if (i < N_NODES) {
        int rp = g_rowptr[i] + pref[i >> 10];
        g_rowptr[i] = rp;
        g_next[i] = rp;
    }
    if (i == 0) g_rowptr[N_NODES] = pref[NB_SCAN];
}

__global__ void k_fill(const int* __restrict__ senders, const int* __restrict__ receivers,
                       const float* __restrict__ edges) {
    int e = blockIdx.x * blockDim.x + threadIdx.x;
    if (e < N_EDGES) {
        int s = senders[e];
        int p = atomicAdd(&g_next[s], 1);
        g_csr_recv[p] = receivers[e];
        g_csr_w[p] = edges[e];
    }
}

// ---------------- fused fp16 Laplacian matvec + Chebyshev combine ----------------
// T_out = s*(deg*x - sum w x[recv]) - (mode ? T_prev : 0),  s = (mode?2:1)/maxkey
__global__ __launch_bounds__(256) void k_spmv16(int in_s, int prev_s, int out_s, int mode) {
    const __half* x = g_T16[in_s];
    const __half* prev = g_T16[prev_s];
    __half* o = g_T16[out_s];

    int warp = (blockIdx.x * blockDim.x + threadIdx.x) >> 5;
    int lane = threadIdx.x & 31;
    if (warp >= N_NODES) return;

    int beg = g_rowptr[warp], end = g_rowptr[warp + 1];
    int c4 = lane * 4;
    float ax = 0.f, ay = 0.f, az = 0.f, aw = 0.f;

    int e = beg;
    for (; e + 2 <= end; e += 2) {
        int r0 = g_csr_recv[e], r1 = g_csr_recv[e + 1];
        float w0 = g_csr_w[e], w1 = g_csr_w[e + 1];
        uint2 v0 = *(const uint2*)(x + (size_t)r0 * C + c4);
        uint2 v1 = *(const uint2*)(x + (size_t)r1 * C + c4);
        float2 f0a = __half22float2(*(__half2*)&v0.x), f0b = __half22float2(*(__half2*)&v0.y);
        float2 f1a = __half22float2(*(__half2*)&v1.x), f1b = __half22float2(*(__half2*)&v1.y);
        ax += w0 * f0a.x + w1 * f1a.x;
        ay += w0 * f0a.y + w1 * f1a.y;
        az += w0 * f0b.x + w1 * f1b.x;
        aw += w0 * f0b.y + w1 * f1b.y;
    }
    if (e < end) {
        int r0 = g_csr_recv[e];
        float w0 = g_csr_w[e];
        uint2 v0 = *(const uint2*)(x + (size_t)r0 * C + c4);
        float2 f0a = __half22float2(*(__half2*)&v0.x), f0b = __half22float2(*(__half2*)&v0.y);
        ax += w0 * f0a.x; ay += w0 * f0a.y; az += w0 * f0b.x; aw += w0 * f0b.y;
    }

    float m = funkey(g_maxkey);
    float s = (mode ? 2.0f : 1.0f) / m;
    float d = g_deg[warp];
    uint2 xv = *(const uint2*)(x + (size_t)warp * C + c4);
    float2 xa = __half22float2(*(__half2*)&xv.x), xb = __half22float2(*(__half2*)&xv.y);
    float rx = s * (d * xa.x - ax);
    float ry = s * (d * xa.y - ay);
    float rz = s * (d * xb.x - az);
    float rw = s * (d * xb.y - aw);
    if (mode) {
        uint2 pv = *(const uint2*)(prev + (size_t)warp * C + c4);
        float2 pa = __half22float2(*(__half2*)&pv.x), pb = __half22float2(*(__half2*)&pv.y);
        rx -= pa.x; ry -= pa.y; rz -= pb.x; rw -= pb.y;
    }
    uint2 ov;
    *(__half2*)&ov.x = __floats2half2_rn(rx, ry);
    *(__half2*)&ov.y = __floats2half2_rn(rz, rw);
    *(uint2*)(o + (size_t)warp * C + c4) = ov;
}

// ---------------- fused fp16 HMMA GEMM: out = sum_k T_k @ W_k + bsum -------------
// CTA: 128x128 tile, 256 threads (8 warps, warp tile 32x64), fp16 smem stride 136.
#define XS_H 136
#define SMEM_GEMM_BYTES (2 * 128 * XS_H * 2)

__global__ __launch_bounds__(256, 2) void k_gemm16(float* __restrict__ out) {
    extern __shared__ __half smh[];
    __half* Xs = smh;                 // [128][136]
    __half* Ws = smh + 128 * XS_H;    // [128][136]

    int tid = threadIdx.x;
    int wid = tid >> 5, lane = tid & 31;
    int g = lane >> 2, t = lane & 3;
    int wm = wid & 3, wn = wid >> 2;  // 4 x 2 warp grid: 32-row x 64-col tiles
    int row0 = blockIdx.x * 128;

    float acc[2][8][4];
    #pragma unroll
    for (int mt = 0; mt < 2; mt++)
        #pragma unroll
        for (int nt = 0; nt < 8; nt++)
            #pragma unroll
            for (int j = 0; j < 4; j++) acc[mt][nt][j] = 0.f;

    for (int kc = 0; kc < KCHEB; kc++) {
        const __half* Xp = g_T16[kc];
        const __half* Wp = g_WT16 + kc * (C * C);

        // stage X/W tiles: 128 rows x 128 halfs each = 2048 uint4 per tile
        #pragma unroll
        for (int i = 0; i < 8; i++) {
            int idx = tid + i * 256;
            int r = idx >> 4, u = idx & 15;
            int row = row0 + r;
            uint4 xv = make_uint4(0u, 0u, 0u, 0u);
            if (row < N_NODES) xv = *(const uint4*)(Xp + (size_t)row * C + u * 8);
            *(uint4*)(Xs + r * XS_H + u * 8) = xv;
            uint4 wv = *(const uint4*)(Wp + r * C + u * 8);
            *(uint4*)(Ws + r * XS_H + u * 8) = wv;
        }
        __syncthreads();

        #pragma unroll
        for (int ks = 0; ks < 8; ks++) {
            int kb = ks * 16;
            uint32_t a[2][4];
            #pragma unroll
            for (int mt = 0; mt < 2; mt++) {
                const __half* xr = Xs + (wm * 32 + mt * 16 + g) * XS_H + kb;
                a[mt][0] = *(const uint32_t*)(xr + 2 * t);
                a[mt][1] = *(const uint32_t*)(xr + 8 * XS_H + 2 * t);
                a[mt][2] = *(const uint32_t*)(xr + 2 * t + 8);
                a[mt][3] = *(const uint32_t*)(xr + 8 * XS_H + 2 * t + 8);
            }
            #pragma unroll
            for (int nt = 0; nt < 8; nt++) {
                const __half* wr = Ws + (wn * 64 + nt * 8 + g) * XS_H + kb;
                uint32_t b0 = *(const uint32_t*)(wr + 2 * t);
                uint32_t b1 = *(const uint32_t*)(wr + 2 * t + 8);
                mma_f16(acc[0][nt], a[0][0], a[0][1], a[0][2], a[0][3], b0, b1);
                mma_f16(acc[1][nt], a[1][0], a[1][1], a[1][2], a[1][3], b0, b1);
            }
        }
        __syncthreads();
    }

    // epilogue with bias
    #pragma unroll
    for (int mt = 0; mt < 2; mt++) {
        int row_lo = row0 + wm * 32 + mt * 16 + g;
        int row_hi = row_lo + 8;
        #pragma unroll
        for (int nt = 0; nt < 8; nt++) {
            int col = wn * 64 + nt * 8 + 2 * t;
            float b0 = g_bsum[col], b1 = g_bsum[col + 1];
            if (row_lo < N_NODES) {
                float2 v = make_float2(acc[mt][nt][0] + b0, acc[mt][nt][1] + b1);
                *(float2*)(out + (size_t)row_lo * C + col) = v;
            }
            if (row_hi < N_NODES) {
                float2 v = make_float2(acc[mt][nt][2] + b0, acc[mt][nt][3] + b1);
                *(float2*)(out + (size_t)row_hi * C + col) = v;
            }
        }
    }
}

// ---------------- launch ----------------
extern "C" void kernel_launch(void* const* d_in, const int* in_sizes, int n_in,
                              void* d_out, int out_size) {
    const float* nodes     = (const float*)d_in[0];
    const float* edges     = (const float*)d_in[1];
    const int*   senders   = (const int*)d_in[2];
    const int*   receivers = (const int*)d_in[3];
    const float* W         = (const float*)d_in[4];
    const float* b_dense   = (const float*)d_in[5];
    const float* bias      = (const float*)d_in[6];
    float* out = (float*)d_out;

    const int NBLK_I = (N_NODES * C / 2 + 255) / 256;   // 12500
    const int NBLK_N = (N_NODES + 255) / 256;
    const int NBLK_E = (N_EDGES + 255) / 256;
    const int NBLK_S = (N_NODES * 32 + 255) / 256;

    cudaFuncSetAttribute(k_gemm16, cudaFuncAttributeMaxDynamicSharedMemorySize,
                         SMEM_GEMM_BYTES);

    k_init<<<NBLK_I, 256>>>(nodes, W, b_dense, bias);
    k_edge_stats<<<NBLK_E, 256>>>(edges, senders);
    k_scan1<<<NB_SCAN, 1024>>>();
    k_scan23<<<NBLK_N, 256>>>();
    k_fill<<<NBLK_E, 256>>>(senders, receivers, edges);

    // Chebyshev recurrence in fp16: T1..T5
    k_spmv16<<<NBLK_S, 256>>>(0, 0, 1, 0);
    k_spmv16<<<NBLK_S, 256>>>(1, 0, 2, 1);
    k_spmv16<<<NBLK_S, 256>>>(2, 1, 3, 1);
    k_spmv16<<<NBLK_S, 256>>>(3, 2, 4, 1);
    k_spmv16<<<NBLK_S, 256>>>(4, 3, 5, 1);

    // out = sum_k T_k @ W_k + (sum_k b_dense[k] + bias)
    k_gemm16<<<NTILES, 256, SMEM_GEMM_BYTES>>>(out);
}

// round 5
// speedup vs baseline: 2.7244x; 1.1478x over previous
#include <cuda_runtime.h>
#include <cuda_fp16.h>
#include <cstdint>

#define N_NODES 50000
#define N_EDGES 800000
#define C 128
#define KCHEB 6
#define NB_SCAN ((N_NODES + 1023) / 1024)
#define NTILES ((N_NODES + 127) / 128)

// ---------------- scratch (device globals: no allocation allowed) ----------------
__device__ float    g_deg[N_NODES];
__device__ int      g_cnt[N_NODES];
__device__ int      g_rowptr[N_NODES + 1];
__device__ int      g_next[N_NODES];
__device__ int      g_part[NB_SCAN];
__device__ int2     g_csr[N_EDGES];              // {recv, weight bits}
__device__ __half   g_T16[KCHEB][N_NODES * C];   // T0..T5 in fp16
__device__ __half   g_WT16[KCHEB * C * C];       // WT16[k][n][cin] = W[k][cin][n]
__device__ unsigned g_maxkey;
__device__ float    g_bsum[C];                   // sum_k b_dense[k] + bias

// ---------------- helpers ----------------
__device__ __forceinline__ unsigned fkey(float f) {
    unsigned u = __float_as_uint(f);
    return (u & 0x80000000u) ? ~u : (u | 0x80000000u);
}
__device__ __forceinline__ float funkey(unsigned k) {
    return (k & 0x80000000u) ? __uint_as_float(k & 0x7fffffffu) : __uint_as_float(~k);
}

__device__ __forceinline__ void blockMaxKey(unsigned k) {
    int lane = threadIdx.x & 31, wid = threadIdx.x >> 5;
    #pragma unroll
    for (int o = 16; o > 0; o >>= 1) {
        unsigned x = __shfl_down_sync(0xffffffffu, k, o);
        k = k > x ? k : x;
    }
    __shared__ unsigned sm[32];
    if (lane == 0) sm[wid] = k;
    __syncthreads();
    if (wid == 0) {
        int nw = (blockDim.x + 31) >> 5;
        k = (lane < nw) ? sm[lane] : 0u;
        #pragma unroll
        for (int o = 16; o > 0; o >>= 1) {
            unsigned x = __shfl_down_sync(0xffffffffu, k, o);
            k = k > x ? k : x;
        }
        if (lane == 0) atomicMax(&g_maxkey, k);
    }
}

__device__ __forceinline__ void mma_f16(float* c, uint32_t a0, uint32_t a1,
                                        uint32_t a2, uint32_t a3,
                                        uint32_t b0, uint32_t b1) {
    asm volatile(
        "mma.sync.aligned.m16n8k16.row.col.f32.f16.f16.f32 "
        "{%0,%1,%2,%3}, {%4,%5,%6,%7}, {%8,%9}, {%0,%1,%2,%3};"
        : "+f"(c[0]), "+f"(c[1]), "+f"(c[2]), "+f"(c[3])
        : "r"(a0), "r"(a1), "r"(a2), "r"(a3), "r"(b0), "r"(b1));
}

__device__ __forceinline__ uint32_t smem_u32(const void* p) {
    uint32_t a;
    asm("{ .reg .u64 t; cvta.to.shared.u64 t, %1; cvt.u32.u64 %0, t; }" : "=r"(a) : "l"(p));
    return a;
}

#define CP_ASYNC16(dst, src, sz) \
    asm volatile("cp.async.cg.shared.global [%0], [%1], 16, %2;" \
        :: "r"(dst), "l"(src), "r"(sz) : "memory")
#define CP_COMMIT() asm volatile("cp.async.commit_group;" ::: "memory")
#define CP_WAIT0()  asm volatile("cp.async.wait_group 0;" ::: "memory")

// ---------------- merged setup: zero, bsum, maxkey, W^T fp16, nodes->fp16 --------
__global__ void k_init(const float* __restrict__ nodes, const float* __restrict__ W,
                       const float* __restrict__ bd, const float* __restrict__ bias) {
    unsigned i = blockIdx.x * blockDim.x + threadIdx.x;
    if (i < (unsigned)(N_NODES * C / 2)) {
        float2 f = *(const float2*)(nodes + (size_t)i * 2);
        *(__half2*)&g_T16[0][(size_t)i * 2] = __floats2half2_rn(f.x, f.y);
    }
    if (i < (unsigned)(KCHEB * C * C)) {
        unsigned kc = i >> 14, rem = i & 16383;
        unsigned n = rem >> 7, k = rem & 127;
        g_WT16[i] = __float2half(W[kc * C * C + k * C + n]);
    }
    if (i < N_NODES) { g_deg[i] = 0.f; g_cnt[i] = 0; }
    if (i < C) {
        float s = bias[i];
        #pragma unroll
        for (int k = 0; k < KCHEB; k++) s += bd[k * C + i];
        g_bsum[i] = s;
    }
    if (i == 0) g_maxkey = 0u;
}

__global__ void k_edge_stats(const float* __restrict__ edges, const int* __restrict__ senders) {
    int e = blockIdx.x * blockDim.x + threadIdx.x;
    unsigned key = 0u;
    if (e < N_EDGES) {
        float w = edges[e];
        int s = senders[e];
        atomicAdd(&g_deg[s], w);
        atomicAdd(&g_cnt[s], 1);
        key = fkey(-w);
    }
    blockMaxKey(key);
}

__global__ void k_scan1() {
    int t = threadIdx.x;
    int i = blockIdx.x * 1024 + t;
    int v = (i < N_NODES) ? g_cnt[i] : 0;
    unsigned dkey = (i < N_NODES) ? fkey(g_deg[i]) : 0u;
    int lane = t & 31, wid = t >> 5;
    int incl = v;
    #pragma unroll
    for (int o = 1; o < 32; o <<= 1) {
        int n = __shfl_up_sync(0xffffffffu, incl, o);
        if (lane >= o) incl += n;
    }
    __shared__ int ws[32];
    if (lane == 31) ws[wid] = incl;
    __syncthreads();
    if (wid == 0) {
        int x = ws[lane];
        int ix = x;
        #pragma unroll
        for (int o = 1; o < 32; o <<= 1) {
            int n = __shfl_up_sync(0xffffffffu, ix, o);
            if (lane >= o) ix += n;
        }
        ws[lane] = ix - x;
    }
    __syncthreads();
    int excl = incl - v + ws[wid];
    if (i < N_NODES) g_rowptr[i] = excl;
    if (t == 1023) g_part[blockIdx.x] = excl + v;
    __syncthreads();
    blockMaxKey(dkey);
}

__global__ void k_scan23() {
    __shared__ int pref[NB_SCAN + 1];
    __shared__ int raw[NB_SCAN];
    int t = threadIdx.x;
    if (t < NB_SCAN) raw[t] = g_part[t];
    __syncthreads();
    if (t == 0) {
        int c = 0;
        for (int b = 0; b < NB_SCAN; b++) { pref[b] = c; c += raw[b]; }
        pref[NB_SCAN] = c;
    }
    __syncthreads();
    int i = blockIdx.x * blockDim.x + t;
    if (i < N_NODES) {
        int rp = g_rowptr[i] + pref[i >> 10];
        g_rowptr[i] = rp;
        g_next[i] = rp;
    }
    if (i == 0) g_rowptr[N_NODES] = pref[NB_SCAN];
}

__global__ void k_fill(const int* __restrict__ senders, const int* __restrict__ receivers,
                       const float* __restrict__ edges) {
    int e = blockIdx.x * blockDim.x + threadIdx.x;
    if (e < N_EDGES) {
        int s = senders[e];
        int p = atomicAdd(&g_next[s], 1);
        g_csr[p] = make_int2(receivers[e], __float_as_int(edges[e]));
    }
}

// ---------------- fused fp16 Laplacian matvec + Chebyshev combine ----------------
// half-warp per node; lane covers 8 halfs (uint4); 2-edge unroll.
__global__ __launch_bounds__(256) void k_spmv16(int in_s, int prev_s, int out_s, int mode) {
    const __half* x = g_T16[in_s];
    const __half* prev = g_T16[prev_s];
    __half* o = g_T16[out_s];

    int node = (blockIdx.x * blockDim.x + threadIdx.x) >> 4;
    int l = threadIdx.x & 15;
    if (node >= N_NODES) return;

    int beg = g_rowptr[node], end = g_rowptr[node + 1];
    int c8 = l * 8;
    float a0 = 0.f, a1 = 0.f, a2 = 0.f, a3 = 0.f, a4 = 0.f, a5 = 0.f, a6 = 0.f, a7 = 0.f;

    int e = beg;
    for (; e + 2 <= end; e += 2) {
        int2 e0 = g_csr[e], e1 = g_csr[e + 1];
        float w0 = __int_as_float(e0.y), w1 = __int_as_float(e1.y);
        uint4 v0 = *(const uint4*)(x + (size_t)e0.x * C + c8);
        uint4 v1 = *(const uint4*)(x + (size_t)e1.x * C + c8);
        float2 p0 = __half22float2(*(__half2*)&v0.x), q0 = __half22float2(*(__half2*)&v1.x);
        float2 p1 = __half22float2(*(__half2*)&v0.y), q1 = __half22float2(*(__half2*)&v1.y);
        float2 p2 = __half22float2(*(__half2*)&v0.z), q2 = __half22float2(*(__half2*)&v1.z);
        float2 p3 = __half22float2(*(__half2*)&v0.w), q3 = __half22float2(*(__half2*)&v1.w);
        a0 += w0 * p0.x + w1 * q0.x;  a1 += w0 * p0.y + w1 * q0.y;
        a2 += w0 * p1.x + w1 * q1.x;  a3 += w0 * p1.y + w1 * q1.y;
        a4 += w0 * p2.x + w1 * q2.x;  a5 += w0 * p2.y + w1 * q2.y;
        a6 += w0 * p3.x + w1 * q3.x;  a7 += w0 * p3.y + w1 * q3.y;
    }
    if (e < end) {
        int2 e0 = g_csr[e];
        float w0 = __int_as_float(e0.y);
        uint4 v0 = *(const uint4*)(x + (size_t)e0.x * C + c8);
        float2 p0 = __half22float2(*(__half2*)&v0.x);
        float2 p1 = __half22float2(*(__half2*)&v0.y);
        float2 p2 = __half22float2(*(__half2*)&v0.z);
        float2 p3 = __half22float2(*(__half2*)&v0.w);
        a0 += w0 * p0.x; a1 += w0 * p0.y; a2 += w0 * p1.x; a3 += w0 * p1.y;
        a4 += w0 * p2.x; a5 += w0 * p2.y; a6 += w0 * p3.x; a7 += w0 * p3.y;
    }

    float m = funkey(g_maxkey);
    float s = (mode ? 2.0f : 1.0f) / m;
    float d = g_deg[node];
    uint4 xv = *(const uint4*)(x + (size_t)node * C + c8);
    float2 x0 = __half22float2(*(__half2*)&xv.x);
    float2 x1 = __half22float2(*(__half2*)&xv.y);
    float2 x2 = __half22float2(*(__half2*)&xv.z);
    float2 x3 = __half22float2(*(__half2*)&xv.w);
    float r0 = s * (d * x0.x - a0), r1 = s * (d * x0.y - a1);
    float r2 = s * (d * x1.x - a2), r3 = s * (d * x1.y - a3);
    float r4 = s * (d * x2.x - a4), r5 = s * (d * x2.y - a5);
    float r6 = s * (d * x3.x - a6), r7 = s * (d * x3.y - a7);
    if (mode) {
        uint4 pv = *(const uint4*)(prev + (size_t)node * C + c8);
        float2 p0 = __half22float2(*(__half2*)&pv.x);
        float2 p1 = __half22float2(*(__half2*)&pv.y);
        float2 p2 = __half22float2(*(__half2*)&pv.z);
        float2 p3 = __half22float2(*(__half2*)&pv.w);
        r0 -= p0.x; r1 -= p0.y; r2 -= p1.x; r3 -= p1.y;
        r4 -= p2.x; r5 -= p2.y; r6 -= p3.x; r7 -= p3.y;
    }
    uint4 ov;
    *(__half2*)&ov.x = __floats2half2_rn(r0, r1);
    *(__half2*)&ov.y = __floats2half2_rn(r2, r3);
    *(__half2*)&ov.z = __floats2half2_rn(r4, r5);
    *(__half2*)&ov.w = __floats2half2_rn(r6, r7);
    *(uint4*)(o + (size_t)node * C + c8) = ov;
}

// ------- fused fp16 HMMA GEMM, cp.async double-buffered over the 6 terms --------
#define XS_H 136
#define TILE_HALFS (128 * XS_H)              // one matrix tile in halfs
#define STAGE_HALFS (2 * TILE_HALFS)         // X + W
#define SMEM_GEMM_BYTES (2 * STAGE_HALFS * 2)  // 2 stages, fp16

__global__ __launch_bounds__(256) void k_gemm16(float* __restrict__ out) {
    extern __shared__ __half smh[];
    uint32_t sb = smem_u32(smh);

    int tid = threadIdx.x;
    int wid = tid >> 5, lane = tid & 31;
    int g = lane >> 2, t = lane & 3;
    int wm = wid & 3, wn = wid >> 2;
    int row0 = blockIdx.x * 128;

    // stage term kc into buffer b (async)
    auto stage = [&](int b, int kc) {
        const __half* Xp = g_T16[kc];
        const __half* Wp = g_WT16 + kc * (C * C);
        uint32_t xb = sb + (uint32_t)b * STAGE_HALFS * 2;
        uint32_t wb = xb + TILE_HALFS * 2;
        #pragma unroll
        for (int i = 0; i < 8; i++) {
            int idx = tid + i * 256;
            int r = idx >> 4, u = idx & 15;
            int row = row0 + r;
            int ok = (row < N_NODES) ? 16 : 0;
            const __half* xs = Xp + (size_t)(ok ? row : 0) * C + u * 8;
            CP_ASYNC16(xb + (uint32_t)(r * XS_H + u * 8) * 2, xs, ok);
            CP_ASYNC16(wb + (uint32_t)(r * XS_H + u * 8) * 2, Wp + r * C + u * 8, 16);
        }
    };

    float acc[2][8][4];
    #pragma unroll
    for (int mt = 0; mt < 2; mt++)
        #pragma unroll
        for (int nt = 0; nt < 8; nt++)
            #pragma unroll
            for (int j = 0; j < 4; j++) acc[mt][nt][j] = 0.f;

    stage(0, 0);
    CP_COMMIT();
    CP_WAIT0();
    __syncthreads();

    int buf = 0;
    for (int kc = 0; kc < KCHEB; kc++) {
        if (kc + 1 < KCHEB) { stage(buf ^ 1, kc + 1); CP_COMMIT(); }

        const __half* Xs = smh + buf * STAGE_HALFS;
        const __half* Ws = Xs + TILE_HALFS;

        #pragma unroll
        for (int ks = 0; ks < 8; ks++) {
            int kb = ks * 16;
            uint32_t a[2][4];
            #pragma unroll
            for (int mt = 0; mt < 2; mt++) {
                const __half* xr = Xs + (wm * 32 + mt * 16 + g) * XS_H + kb;
                a[mt][0] = *(const uint32_t*)(xr + 2 * t);
                a[mt][1] = *(const uint32_t*)(xr + 8 * XS_H + 2 * t);
                a[mt][2] = *(const uint32_t*)(xr + 2 * t + 8);
                a[mt][3] = *(const uint32_t*)(xr + 8 * XS_H + 2 * t + 8);
            }
            #pragma unroll
            for (int nt = 0; nt < 8; nt++) {
                const __half* wr = Ws + (wn * 64 + nt * 8 + g) * XS_H + kb;
                uint32_t b0 = *(const uint32_t*)(wr + 2 * t);
                uint32_t b1 = *(const uint32_t*)(wr + 2 * t + 8);
                mma_f16(acc[0][nt], a[0][0], a[0][1], a[0][2], a[0][3], b0, b1);
                mma_f16(acc[1][nt], a[1][0], a[1][1], a[1][2], a[1][3], b0, b1);
            }
        }

        if (kc + 1 < KCHEB) CP_WAIT0();
        __syncthreads();
        buf ^= 1;
    }

    #pragma unroll
    for (int mt = 0; mt < 2; mt++) {
        int row_lo = row0 + wm * 32 + mt * 16 + g;
        int row_hi = row_lo + 8;
        #pragma unroll
        for (int nt = 0; nt < 8; nt++) {
            int col = wn * 64 + nt * 8 + 2 * t;
            float b0 = g_bsum[col], b1 = g_bsum[col + 1];
            if (row_lo < N_NODES) {
                float2 v = make_float2(acc[mt][nt][0] + b0, acc[mt][nt][1] + b1);
                *(float2*)(out + (size_t)row_lo * C + col) = v;
            }
            if (row_hi < N_NODES) {
                float2 v = make_float2(acc[mt][nt][2] + b0, acc[mt][nt][3] + b1);
                *(float2*)(out + (size_t)row_hi * C + col) = v;
            }
        }
    }
}

// ---------------- launch ----------------
extern "C" void kernel_launch(void* const* d_in, const int* in_sizes, int n_in,
                              void* d_out, int out_size) {
    const float* nodes     = (const float*)d_in[0];
    const float* edges     = (const float*)d_in[1];
    const int*   senders   = (const int*)d_in[2];
    const int*   receivers = (const int*)d_in[3];
    const float* W         = (const float*)d_in[4];
    const float* b_dense   = (const float*)d_in[5];
    const float* bias      = (const float*)d_in[6];
    float* out = (float*)d_out;

    const int NBLK_I = (N_NODES * C / 2 + 255) / 256;
    const int NBLK_N = (N_NODES + 255) / 256;
    const int NBLK_E = (N_EDGES + 255) / 256;
    const int NBLK_S = (N_NODES * 16 + 255) / 256;   // half-warp per node

    cudaFuncSetAttribute(k_gemm16, cudaFuncAttributeMaxDynamicSharedMemorySize,
                         SMEM_GEMM_BYTES);

    k_init<<<NBLK_I, 256>>>(nodes, W, b_dense, bias);
    k_edge_stats<<<NBLK_E, 256>>>(edges, senders);
    k_scan1<<<NB_SCAN, 1024>>>();
    k_scan23<<<NBLK_N, 256>>>();
    k_fill<<<NBLK_E, 256>>>(senders, receivers, edges);

    k_spmv16<<<NBLK_S, 256>>>(0, 0, 1, 0);
    k_spmv16<<<NBLK_S, 256>>>(1, 0, 2, 1);
    k_spmv16<<<NBLK_S, 256>>>(2, 1, 3, 1);
    k_spmv16<<<NBLK_S, 256>>>(3, 2, 4, 1);
    k_spmv16<<<NBLK_S, 256>>>(4, 3, 5, 1);

    k_gemm16<<<NTILES, 256, SMEM_GEMM_BYTES>>>(out);
}